// round 12
// baseline (speedup 1.0000x reference)
#include <cuda_runtime.h>
#include <cuda_fp16.h>
#include <cuda_bf16.h>
#include <math.h>

// Problem constants (fixed by the dataset)
#define BB 2
#define CC 256
#define HH 200
#define WW 200
#define HWSZ (HH * WW)          // 40000
#define OUT_H 7
#define OUT_W 7
#define GSAMP 2
#define NSAMP (OUT_H * GSAMP * OUT_W * GSAMP)  // 196
#define SPATIAL_SCALE 0.25f
#define NBINS (OUT_H * OUT_W)   // 49
#define HALF_C 128              // channels per CTA
#define RPITCH 132              // 128 + 4 floats per staging row
#define PASS1_BINS 25           // bins 0..24 in pass 0, 25..48 in pass 1

// NHWC fp16 scratch: 2*200*200*256 halves = 40.96 MB (static device array: allowed)
__device__ __align__(16) __half g_featT[(size_t)BB * HWSZ * CC];

__device__ __forceinline__ __half2 u2h(unsigned int u) {
    __half2 h; *reinterpret_cast<unsigned int*>(&h) = u; return h;
}
__device__ __forceinline__ unsigned int h2u(__half2 h) {
    return *reinterpret_cast<unsigned int*>(&h);
}

// ---------------------------------------------------------------------------
// Kernel 1: NCHW fp32 -> NHWC fp16 transpose (tiled 32x32, coalesced, half2
// vectorized stores). ~123MB DRAM traffic, memory bound.
// ---------------------------------------------------------------------------
__global__ void nchw_to_nhwc_half_kernel(const float* __restrict__ in) {
    __shared__ float tile[32][33];
    const int b  = blockIdx.z;
    const int p0 = blockIdx.x * 32;   // spatial tile origin
    const int c0 = blockIdx.y * 32;   // channel tile origin
    const int tx = threadIdx.x;       // 0..31
    const int ty = threadIdx.y;       // 0..7
    const int tid = ty * 32 + tx;

    const float* src = in + (size_t)b * CC * HWSZ;
    __half* dst = g_featT + (size_t)b * HWSZ * CC;

    #pragma unroll
    for (int i = 0; i < 32; i += 8)
        tile[ty + i][tx] = src[(size_t)(c0 + ty + i) * HWSZ + (p0 + tx)];
    __syncthreads();

    #pragma unroll
    for (int it = 0; it < 2; it++) {
        const int e  = it * 256 + tid;
        const int pl = e >> 4;        // local position 0..31
        const int h  = e & 15;        // half2 index within 32 channels
        const float f0 = tile[2 * h][pl];
        const float f1 = tile[2 * h + 1][pl];
        __half2 v = __floats2half2_rn(f0, f1);
        *reinterpret_cast<__half2*>(dst + (size_t)(p0 + pl) * CC + c0 + 2 * h) = v;
    }
}

// ---------------------------------------------------------------------------
// Kernel 2: RoIAlignRotated gather, fp16 features + half2 bilinear math.
// grid = 2N (channel halves), 256 threads, __launch_bounds__(256,7):
// smem ~19.5KB (two-pass staging) + regs<=36  ->  7 CTAs/SM (87.5% occ).
// Thread t: oct q = t & 15 (8 local channels), bin group bg = t >> 4.
// ---------------------------------------------------------------------------
__global__ __launch_bounds__(256, 7)
void roi_align_rotated_kernel(const float* __restrict__ rois,
                              float* __restrict__ out,
                              int N) {
    __shared__ uint4 s_wh[NSAMP];                 // 4 duplicated-half2 weights
    __shared__ int4  s_i[NSAMP];                  // oct (16B) indices
    __shared__ float s_out[PASS1_BINS * RPITCH];  // 13200 B (reused per pass)

    const int n    = blockIdx.x >> 1;
    const int half = blockIdx.x & 1;
    const int tid  = threadIdx.x;
    const int q    = tid & 15;                // local oct 0..15
    const int bg   = tid >> 4;                // 0..15

    // --- roi params (broadcast) ---
    const float* R = rois + (size_t)n * 6;
    const int   b     = (int)R[0];
    const float cx    = R[1] * SPATIAL_SCALE;
    const float cy    = R[2] * SPATIAL_SCALE;
    const float rw    = fmaxf(R[3] * SPATIAL_SCALE, 1.0f);
    const float rh    = fmaxf(R[4] * SPATIAL_SCALE, 1.0f);
    const float theta = R[5];
    const float cost  = cosf(theta);
    const float sint  = sinf(theta);
    const float bin_h = rh * (1.0f / OUT_H);
    const float bin_w = rw * (1.0f / OUT_W);

    // --- Phase A: sample-point precompute (reference semantics exactly) ---
    if (tid < NSAMP) {
        const int s = tid;
        const int r = s / (OUT_W * GSAMP);
        const int p = s % (OUT_W * GSAMP);
        const float sy = ((float)r + 0.5f) * (1.0f / GSAMP);
        const float sx = ((float)p + 0.5f) * (1.0f / GSAMP);
        const float yy = -rh * 0.5f + sy * bin_h;
        const float xx = -rw * 0.5f + sx * bin_w;
        const float y = yy * cost - xx * sint + cy;
        const float x = yy * sint + xx * cost + cx;

        const bool inside = (y >= -1.0f) && (y <= (float)HH) &&
                            (x >= -1.0f) && (x <= (float)WW);

        const float yc = fmaxf(y, 0.0f);
        const float xc = fmaxf(x, 0.0f);
        const float fy = floorf(yc);
        const float fx = floorf(xc);
        int yl = min((int)fy, HH - 1);
        int xl = min((int)fx, WW - 1);
        const int yh = min(yl + 1, HH - 1);
        const int xh = min(xl + 1, WW - 1);
        const float ly = (fy >= (float)(HH - 1)) ? 0.0f : (yc - (float)yl);
        const float lx = (fx >= (float)(WW - 1)) ? 0.0f : (xc - (float)xl);
        const float hy = 1.0f - ly;
        const float hx = 1.0f - lx;

        float w1 = hy * hx, w2 = hy * lx, w3 = ly * hx, w4 = ly * lx;
        if (!inside) { w1 = 0.f; w2 = 0.f; w3 = 0.f; w4 = 0.f; }

        uint4 wh;
        wh.x = h2u(__float2half2_rn(w1));   // (w1, w1)
        wh.y = h2u(__float2half2_rn(w2));
        wh.z = h2u(__float2half2_rn(w3));
        wh.w = h2u(__float2half2_rn(w4));

        // index in oct (16B) units: pos * (CC/8) = pos * 32
        const int base = b * HWSZ;
        int4 idx;
        idx.x = (base + yl * WW + xl) * (CC / 8);
        idx.y = (base + yl * WW + xh) * (CC / 8);
        idx.z = (base + yh * WW + xl) * (CC / 8);
        idx.w = (base + yh * WW + xh) * (CC / 8);
        s_i[s]  = idx;
        s_wh[s] = wh;
    }
    __syncthreads();

    const uint4* __restrict__ ft8 =
        reinterpret_cast<const uint4*>(g_featT) + (half * 16 + q);
    float* outp = out + (size_t)n * (CC * NBINS) + (size_t)half * (HALF_C * NBINS);

    // --- Two passes over the 49 bins, reusing half-size staging buffer ---
    #pragma unroll 1
    for (int pass = 0; pass < 2; pass++) {
        const int jbase = pass ? PASS1_BINS : 0;
        const int count = pass ? (NBINS - PASS1_BINS) : PASS1_BINS;

        // Phase B: gather + half2 bilinear + fp32 cross-sample accumulation
        #pragma unroll 1
        for (int jj = jbase + bg; jj < jbase + count; jj += 16) {
            const int ph = jj / OUT_W;
            const int pw = jj - ph * OUT_W;
            const int s00 = (2 * ph) * (OUT_W * GSAMP) + 2 * pw;

            float acc[8];
            #pragma unroll
            for (int k = 0; k < 8; k++) acc[k] = 0.0f;

            #pragma unroll
            for (int iy = 0; iy < GSAMP; iy++) {
                #pragma unroll
                for (int ix = 0; ix < GSAMP; ix++) {
                    const int s = s00 + iy * (OUT_W * GSAMP) + ix;
                    const int4  ii = s_i[s];    // LDS.128 broadcast
                    const uint4 wh = s_wh[s];   // LDS.128 broadcast
                    const __half2 w1 = u2h(wh.x);
                    const __half2 w2 = u2h(wh.y);
                    const __half2 w3 = u2h(wh.z);
                    const __half2 w4 = u2h(wh.w);
                    const uint4 u1 = __ldg(ft8 + ii.x);
                    const uint4 u2 = __ldg(ft8 + ii.y);
                    const uint4 u3 = __ldg(ft8 + ii.z);
                    const uint4 u4 = __ldg(ft8 + ii.w);
                    const __half2* h1 = reinterpret_cast<const __half2*>(&u1);
                    const __half2* h2 = reinterpret_cast<const __half2*>(&u2);
                    const __half2* h3 = reinterpret_cast<const __half2*>(&u3);
                    const __half2* h4 = reinterpret_cast<const __half2*>(&u4);
                    #pragma unroll
                    for (int k = 0; k < 4; k++) {
                        __half2 t = __hmul2(h1[k], w1);
                        t = __hfma2(h2[k], w2, t);
                        t = __hfma2(h3[k], w3, t);
                        t = __hfma2(h4[k], w4, t);
                        const float2 f = __half22float2(t);
                        acc[2*k]   += f.x;
                        acc[2*k+1] += f.y;
                    }
                }
            }
            float4 r0 = make_float4(acc[0] * 0.25f, acc[1] * 0.25f,
                                    acc[2] * 0.25f, acc[3] * 0.25f);
            float4 r1 = make_float4(acc[4] * 0.25f, acc[5] * 0.25f,
                                    acc[6] * 0.25f, acc[7] * 0.25f);
            float* row = &s_out[(jj - jbase) * RPITCH + 8 * q];
            *reinterpret_cast<float4*>(row)     = r0;
            *reinterpret_cast<float4*>(row + 4) = r1;
        }
        __syncthreads();

        // Phase C: coalesced store of this pass's bins for all 128 channels
        #pragma unroll 1
        for (int i = tid; i < HALF_C * count; i += 256) {
            const int c  = i / count;       // local channel 0..127
            const int jb = i - c * count;   // bin within pass
            outp[c * NBINS + jbase + jb] = s_out[jb * RPITCH + c];
        }
        if (pass == 0) __syncthreads();     // protect staging reuse
    }
}

// ---------------------------------------------------------------------------
extern "C" void kernel_launch(void* const* d_in, const int* in_sizes, int n_in,
                              void* d_out, int out_size) {
    const float* features;
    const float* rois;
    int rois_elems;
    if (in_sizes[0] > in_sizes[1]) {
        features = (const float*)d_in[0];
        rois     = (const float*)d_in[1];
        rois_elems = in_sizes[1];
    } else {
        features = (const float*)d_in[1];
        rois     = (const float*)d_in[0];
        rois_elems = in_sizes[0];
    }
    const int N = rois_elems / 6;

    dim3 tgrid(HWSZ / 32, CC / 32, BB);
    dim3 tblk(32, 8);
    nchw_to_nhwc_half_kernel<<<tgrid, tblk>>>(features);

    roi_align_rotated_kernel<<<N * 2, 256>>>(rois, (float*)d_out, N);
}

// round 13
// speedup vs baseline: 1.7281x; 1.7281x over previous
#include <cuda_runtime.h>
#include <cuda_fp16.h>
#include <cuda_bf16.h>
#include <math.h>

// Problem constants (fixed by the dataset)
#define BB 2
#define CC 256
#define HH 200
#define WW 200
#define HWSZ (HH * WW)          // 40000
#define OUT_H 7
#define OUT_W 7
#define GSAMP 2
#define NSAMP (OUT_H * GSAMP * OUT_W * GSAMP)  // 196
#define SPATIAL_SCALE 0.25f
#define NBINS (OUT_H * OUT_W)   // 49
#define QC 64                   // channels per CTA (quarter)
#define RPITCH 68               // 64 + 4 floats per staging row (16B-aligned rows)

// NHWC fp16 scratch: 2*200*200*256 halves = 40.96 MB (static device array: allowed)
__device__ __align__(16) __half g_featT[(size_t)BB * HWSZ * CC];

__device__ __forceinline__ __half2 u2h(unsigned int u) {
    __half2 h; *reinterpret_cast<unsigned int*>(&h) = u; return h;
}
__device__ __forceinline__ unsigned int h2u(__half2 h) {
    return *reinterpret_cast<unsigned int*>(&h);
}

// ---------------------------------------------------------------------------
// Kernel 1: NCHW fp32 -> NHWC fp16 transpose (tiled 32x32, coalesced, half2
// vectorized stores). Proven conflict-free; ~123MB DRAM traffic.
// ---------------------------------------------------------------------------
__global__ void nchw_to_nhwc_half_kernel(const float* __restrict__ in) {
    __shared__ float tile[32][33];
    const int b  = blockIdx.z;
    const int p0 = blockIdx.x * 32;   // spatial tile origin
    const int c0 = blockIdx.y * 32;   // channel tile origin
    const int tx = threadIdx.x;       // 0..31
    const int ty = threadIdx.y;       // 0..7
    const int tid = ty * 32 + tx;

    const float* src = in + (size_t)b * CC * HWSZ;
    __half* dst = g_featT + (size_t)b * HWSZ * CC;

    #pragma unroll
    for (int i = 0; i < 32; i += 8)
        tile[ty + i][tx] = src[(size_t)(c0 + ty + i) * HWSZ + (p0 + tx)];
    __syncthreads();

    #pragma unroll
    for (int it = 0; it < 2; it++) {
        const int e  = it * 256 + tid;
        const int pl = e >> 4;        // local position 0..31
        const int h  = e & 15;        // half2 index within 32 channels
        const float f0 = tile[2 * h][pl];
        const float f1 = tile[2 * h + 1][pl];
        __half2 v = __floats2half2_rn(f0, f1);
        *reinterpret_cast<__half2*>(dst + (size_t)(p0 + pl) * CC + c0 + 2 * h) = v;
    }
}

// ---------------------------------------------------------------------------
// Kernel 2: RoIAlignRotated gather, fp16 features + half2 bilinear math.
// grid = 4N: CTA = (roi n, 64-channel quarter). 256 threads.
// Thread t: oct q = t & 7 (8 local channels), bin group bg = t >> 3 (0..31),
//           bins j = bg, bg+32 (j < 49).
// launch_bounds(256,6): regs ~39 (NO forced spill — R12 lesson), smem ~19.6KB
// -> 6 CTAs/SM. Finer CTAs cut wave-quantization tail (4000 vs 2000 CTAs).
// ---------------------------------------------------------------------------
__global__ __launch_bounds__(256, 6)
void roi_align_rotated_kernel(const float* __restrict__ rois,
                              float* __restrict__ out,
                              int N) {
    __shared__ uint4 s_wh[NSAMP];             // 4 duplicated-half2 weights
    __shared__ int4  s_i[NSAMP];              // oct (16B) indices
    __shared__ float s_out[NBINS * RPITCH];   // 13328 B

    const int n       = blockIdx.x >> 2;
    const int quarter = blockIdx.x & 3;
    const int tid     = threadIdx.x;
    const int q       = tid & 7;              // local oct 0..7
    const int bg      = tid >> 3;              // 0..31

    // --- roi params (broadcast) ---
    const float* R = rois + (size_t)n * 6;
    const int   b     = (int)R[0];
    const float cx    = R[1] * SPATIAL_SCALE;
    const float cy    = R[2] * SPATIAL_SCALE;
    const float rw    = fmaxf(R[3] * SPATIAL_SCALE, 1.0f);
    const float rh    = fmaxf(R[4] * SPATIAL_SCALE, 1.0f);
    const float theta = R[5];
    const float cost  = cosf(theta);
    const float sint  = sinf(theta);
    const float bin_h = rh * (1.0f / OUT_H);
    const float bin_w = rw * (1.0f / OUT_W);

    // --- Phase A: sample-point precompute (reference semantics exactly) ---
    if (tid < NSAMP) {
        const int s = tid;
        const int r = s / (OUT_W * GSAMP);
        const int p = s % (OUT_W * GSAMP);
        const float sy = ((float)r + 0.5f) * (1.0f / GSAMP);
        const float sx = ((float)p + 0.5f) * (1.0f / GSAMP);
        const float yy = -rh * 0.5f + sy * bin_h;
        const float xx = -rw * 0.5f + sx * bin_w;
        const float y = yy * cost - xx * sint + cy;
        const float x = yy * sint + xx * cost + cx;

        const bool inside = (y >= -1.0f) && (y <= (float)HH) &&
                            (x >= -1.0f) && (x <= (float)WW);

        const float yc = fmaxf(y, 0.0f);
        const float xc = fmaxf(x, 0.0f);
        const float fy = floorf(yc);
        const float fx = floorf(xc);
        int yl = min((int)fy, HH - 1);
        int xl = min((int)fx, WW - 1);
        const int yh = min(yl + 1, HH - 1);
        const int xh = min(xl + 1, WW - 1);
        const float ly = (fy >= (float)(HH - 1)) ? 0.0f : (yc - (float)yl);
        const float lx = (fx >= (float)(WW - 1)) ? 0.0f : (xc - (float)xl);
        const float hy = 1.0f - ly;
        const float hx = 1.0f - lx;

        float w1 = hy * hx, w2 = hy * lx, w3 = ly * hx, w4 = ly * lx;
        if (!inside) { w1 = 0.f; w2 = 0.f; w3 = 0.f; w4 = 0.f; }

        uint4 wh;
        wh.x = h2u(__float2half2_rn(w1));   // (w1, w1)
        wh.y = h2u(__float2half2_rn(w2));
        wh.z = h2u(__float2half2_rn(w3));
        wh.w = h2u(__float2half2_rn(w4));

        // index in oct (16B) units: pos * (CC/8) = pos * 32
        const int base = b * HWSZ;
        int4 idx;
        idx.x = (base + yl * WW + xl) * (CC / 8);
        idx.y = (base + yl * WW + xh) * (CC / 8);
        idx.z = (base + yh * WW + xl) * (CC / 8);
        idx.w = (base + yh * WW + xh) * (CC / 8);
        s_i[s]  = idx;
        s_wh[s] = wh;
    }
    __syncthreads();

    // --- Phase B: fp16 oct gather, half2 bilinear, fp32 cross-sample acc ---
    const uint4* __restrict__ ft8 =
        reinterpret_cast<const uint4*>(g_featT) + (quarter * 8 + q);

    #pragma unroll 1
    for (int j = bg; j < NBINS; j += 32) {
        const int ph = j / OUT_W;
        const int pw = j - ph * OUT_W;
        const int s00 = (2 * ph) * (OUT_W * GSAMP) + 2 * pw;

        float acc[8];
        #pragma unroll
        for (int k = 0; k < 8; k++) acc[k] = 0.0f;

        #pragma unroll
        for (int iy = 0; iy < GSAMP; iy++) {
            #pragma unroll
            for (int ix = 0; ix < GSAMP; ix++) {
                const int s = s00 + iy * (OUT_W * GSAMP) + ix;
                const int4  ii = s_i[s];    // LDS.128 broadcast
                const uint4 wh = s_wh[s];   // LDS.128 broadcast
                const __half2 w1 = u2h(wh.x);
                const __half2 w2 = u2h(wh.y);
                const __half2 w3 = u2h(wh.z);
                const __half2 w4 = u2h(wh.w);
                const uint4 u1 = __ldg(ft8 + ii.x);
                const uint4 u2 = __ldg(ft8 + ii.y);
                const uint4 u3 = __ldg(ft8 + ii.z);
                const uint4 u4 = __ldg(ft8 + ii.w);
                const __half2* h1 = reinterpret_cast<const __half2*>(&u1);
                const __half2* h2 = reinterpret_cast<const __half2*>(&u2);
                const __half2* h3 = reinterpret_cast<const __half2*>(&u3);
                const __half2* h4 = reinterpret_cast<const __half2*>(&u4);
                #pragma unroll
                for (int k = 0; k < 4; k++) {
                    __half2 t = __hmul2(h1[k], w1);
                    t = __hfma2(h2[k], w2, t);
                    t = __hfma2(h3[k], w3, t);
                    t = __hfma2(h4[k], w4, t);
                    const float2 f = __half22float2(t);
                    acc[2*k]   += f.x;
                    acc[2*k+1] += f.y;
                }
            }
        }
        float4 r0 = make_float4(acc[0] * 0.25f, acc[1] * 0.25f,
                                acc[2] * 0.25f, acc[3] * 0.25f);
        float4 r1 = make_float4(acc[4] * 0.25f, acc[5] * 0.25f,
                                acc[6] * 0.25f, acc[7] * 0.25f);
        float* row = &s_out[j * RPITCH + 8 * q];
        *reinterpret_cast<float4*>(row)     = r0;
        *reinterpret_cast<float4*>(row + 4) = r1;
    }
    __syncthreads();

    // --- Phase C: coalesced contiguous store of this quarter's output slab ---
    float* outp = out + (size_t)n * (CC * NBINS) + (size_t)quarter * (QC * NBINS);
    #pragma unroll 1
    for (int i = tid; i < QC * NBINS; i += 256) {
        const int c = i / NBINS;      // local channel 0..63
        const int j = i - c * NBINS;  // bin 0..48
        outp[i] = s_out[j * RPITCH + c];
    }
}

// ---------------------------------------------------------------------------
extern "C" void kernel_launch(void* const* d_in, const int* in_sizes, int n_in,
                              void* d_out, int out_size) {
    const float* features;
    const float* rois;
    int rois_elems;
    if (in_sizes[0] > in_sizes[1]) {
        features = (const float*)d_in[0];
        rois     = (const float*)d_in[1];
        rois_elems = in_sizes[1];
    } else {
        features = (const float*)d_in[1];
        rois     = (const float*)d_in[0];
        rois_elems = in_sizes[0];
    }
    const int N = rois_elems / 6;

    dim3 tgrid(HWSZ / 32, CC / 32, BB);
    dim3 tblk(32, 8);
    nchw_to_nhwc_half_kernel<<<tgrid, tblk>>>(features);

    roi_align_rotated_kernel<<<N * 4, 256>>>(rois, (float*)d_out, N);
}

// round 14
// speedup vs baseline: 1.7398x; 1.0068x over previous
#include <cuda_runtime.h>
#include <cuda_fp16.h>
#include <cuda_bf16.h>
#include <math.h>

// Problem constants (fixed by the dataset)
#define BB 2
#define CC 256
#define HH 200
#define WW 200
#define HWSZ (HH * WW)          // 40000
#define OUT_H 7
#define OUT_W 7
#define GSAMP 2
#define NSAMP (OUT_H * GSAMP * OUT_W * GSAMP)  // 196
#define SPATIAL_SCALE 0.25f
#define NBINS (OUT_H * OUT_W)   // 49
#define QC 64                   // channels per CTA (quarter)
#define RPITCH 68               // 64 + 4 floats per staging row (16B-aligned rows)

// NHWC fp16 scratch: 2*200*200*256 halves = 40.96 MB (static device array: allowed)
__device__ __align__(16) __half g_featT[(size_t)BB * HWSZ * CC];

__device__ __forceinline__ __half2 u2h(unsigned int u) {
    __half2 h; *reinterpret_cast<unsigned int*>(&h) = u; return h;
}
__device__ __forceinline__ unsigned int h2u(__half2 h) {
    return *reinterpret_cast<unsigned int*>(&h);
}

// ---------------------------------------------------------------------------
// Kernel 1: NCHW fp32 -> NHWC fp16 transpose (tiled 32x32, coalesced, half2
// vectorized stores). Proven conflict-free; ~123MB DRAM traffic.
// ---------------------------------------------------------------------------
__global__ void nchw_to_nhwc_half_kernel(const float* __restrict__ in) {
    __shared__ float tile[32][33];
    const int b  = blockIdx.z;
    const int p0 = blockIdx.x * 32;   // spatial tile origin
    const int c0 = blockIdx.y * 32;   // channel tile origin
    const int tx = threadIdx.x;       // 0..31
    const int ty = threadIdx.y;       // 0..7
    const int tid = ty * 32 + tx;

    const float* src = in + (size_t)b * CC * HWSZ;
    __half* dst = g_featT + (size_t)b * HWSZ * CC;

    #pragma unroll
    for (int i = 0; i < 32; i += 8)
        tile[ty + i][tx] = src[(size_t)(c0 + ty + i) * HWSZ + (p0 + tx)];
    __syncthreads();

    #pragma unroll
    for (int it = 0; it < 2; it++) {
        const int e  = it * 256 + tid;
        const int pl = e >> 4;        // local position 0..31
        const int h  = e & 15;        // half2 index within 32 channels
        const float f0 = tile[2 * h][pl];
        const float f1 = tile[2 * h + 1][pl];
        __half2 v = __floats2half2_rn(f0, f1);
        *reinterpret_cast<__half2*>(dst + (size_t)(p0 + pl) * CC + c0 + 2 * h) = v;
    }
}

// ---------------------------------------------------------------------------
// Kernel 2: RoIAlignRotated gather, fp16 features + half2 bilinear math.
// grid = 4N: CTA = (roi n, 64-channel quarter). 256 threads.
// Thread t: oct q = t & 7 (8 local channels), bin group bg = t >> 3 (0..31),
//           bins j = bg, bg+32 (j < 49).
// launch_bounds(256,6): regs ~39 (NO forced spill — R12 lesson), smem ~19.6KB
// -> 6 CTAs/SM. Finer CTAs cut wave-quantization tail (4000 vs 2000 CTAs).
// ---------------------------------------------------------------------------
__global__ __launch_bounds__(256, 6)
void roi_align_rotated_kernel(const float* __restrict__ rois,
                              float* __restrict__ out,
                              int N) {
    __shared__ uint4 s_wh[NSAMP];             // 4 duplicated-half2 weights
    __shared__ int4  s_i[NSAMP];              // oct (16B) indices
    __shared__ float s_out[NBINS * RPITCH];   // 13328 B

    const int n       = blockIdx.x >> 2;
    const int quarter = blockIdx.x & 3;
    const int tid     = threadIdx.x;
    const int q       = tid & 7;              // local oct 0..7
    const int bg      = tid >> 3;              // 0..31

    // --- roi params (broadcast) ---
    const float* R = rois + (size_t)n * 6;
    const int   b     = (int)R[0];
    const float cx    = R[1] * SPATIAL_SCALE;
    const float cy    = R[2] * SPATIAL_SCALE;
    const float rw    = fmaxf(R[3] * SPATIAL_SCALE, 1.0f);
    const float rh    = fmaxf(R[4] * SPATIAL_SCALE, 1.0f);
    const float theta = R[5];
    const float cost  = cosf(theta);
    const float sint  = sinf(theta);
    const float bin_h = rh * (1.0f / OUT_H);
    const float bin_w = rw * (1.0f / OUT_W);

    // --- Phase A: sample-point precompute (reference semantics exactly) ---
    if (tid < NSAMP) {
        const int s = tid;
        const int r = s / (OUT_W * GSAMP);
        const int p = s % (OUT_W * GSAMP);
        const float sy = ((float)r + 0.5f) * (1.0f / GSAMP);
        const float sx = ((float)p + 0.5f) * (1.0f / GSAMP);
        const float yy = -rh * 0.5f + sy * bin_h;
        const float xx = -rw * 0.5f + sx * bin_w;
        const float y = yy * cost - xx * sint + cy;
        const float x = yy * sint + xx * cost + cx;

        const bool inside = (y >= -1.0f) && (y <= (float)HH) &&
                            (x >= -1.0f) && (x <= (float)WW);

        const float yc = fmaxf(y, 0.0f);
        const float xc = fmaxf(x, 0.0f);
        const float fy = floorf(yc);
        const float fx = floorf(xc);
        int yl = min((int)fy, HH - 1);
        int xl = min((int)fx, WW - 1);
        const int yh = min(yl + 1, HH - 1);
        const int xh = min(xl + 1, WW - 1);
        const float ly = (fy >= (float)(HH - 1)) ? 0.0f : (yc - (float)yl);
        const float lx = (fx >= (float)(WW - 1)) ? 0.0f : (xc - (float)xl);
        const float hy = 1.0f - ly;
        const float hx = 1.0f - lx;

        float w1 = hy * hx, w2 = hy * lx, w3 = ly * hx, w4 = ly * lx;
        if (!inside) { w1 = 0.f; w2 = 0.f; w3 = 0.f; w4 = 0.f; }

        uint4 wh;
        wh.x = h2u(__float2half2_rn(w1));   // (w1, w1)
        wh.y = h2u(__float2half2_rn(w2));
        wh.z = h2u(__float2half2_rn(w3));
        wh.w = h2u(__float2half2_rn(w4));

        // index in oct (16B) units: pos * (CC/8) = pos * 32
        const int base = b * HWSZ;
        int4 idx;
        idx.x = (base + yl * WW + xl) * (CC / 8);
        idx.y = (base + yl * WW + xh) * (CC / 8);
        idx.z = (base + yh * WW + xl) * (CC / 8);
        idx.w = (base + yh * WW + xh) * (CC / 8);
        s_i[s]  = idx;
        s_wh[s] = wh;
    }
    __syncthreads();

    // --- Phase B: fp16 oct gather, half2 bilinear, fp32 cross-sample acc ---
    const uint4* __restrict__ ft8 =
        reinterpret_cast<const uint4*>(g_featT) + (quarter * 8 + q);

    #pragma unroll 1
    for (int j = bg; j < NBINS; j += 32) {
        const int ph = j / OUT_W;
        const int pw = j - ph * OUT_W;
        const int s00 = (2 * ph) * (OUT_W * GSAMP) + 2 * pw;

        float acc[8];
        #pragma unroll
        for (int k = 0; k < 8; k++) acc[k] = 0.0f;

        #pragma unroll
        for (int iy = 0; iy < GSAMP; iy++) {
            #pragma unroll
            for (int ix = 0; ix < GSAMP; ix++) {
                const int s = s00 + iy * (OUT_W * GSAMP) + ix;
                const int4  ii = s_i[s];    // LDS.128 broadcast
                const uint4 wh = s_wh[s];   // LDS.128 broadcast
                const __half2 w1 = u2h(wh.x);
                const __half2 w2 = u2h(wh.y);
                const __half2 w3 = u2h(wh.z);
                const __half2 w4 = u2h(wh.w);
                const uint4 u1 = __ldg(ft8 + ii.x);
                const uint4 u2 = __ldg(ft8 + ii.y);
                const uint4 u3 = __ldg(ft8 + ii.z);
                const uint4 u4 = __ldg(ft8 + ii.w);
                const __half2* h1 = reinterpret_cast<const __half2*>(&u1);
                const __half2* h2 = reinterpret_cast<const __half2*>(&u2);
                const __half2* h3 = reinterpret_cast<const __half2*>(&u3);
                const __half2* h4 = reinterpret_cast<const __half2*>(&u4);
                #pragma unroll
                for (int k = 0; k < 4; k++) {
                    __half2 t = __hmul2(h1[k], w1);
                    t = __hfma2(h2[k], w2, t);
                    t = __hfma2(h3[k], w3, t);
                    t = __hfma2(h4[k], w4, t);
                    const float2 f = __half22float2(t);
                    acc[2*k]   += f.x;
                    acc[2*k+1] += f.y;
                }
            }
        }
        float4 r0 = make_float4(acc[0] * 0.25f, acc[1] * 0.25f,
                                acc[2] * 0.25f, acc[3] * 0.25f);
        float4 r1 = make_float4(acc[4] * 0.25f, acc[5] * 0.25f,
                                acc[6] * 0.25f, acc[7] * 0.25f);
        float* row = &s_out[j * RPITCH + 8 * q];
        *reinterpret_cast<float4*>(row)     = r0;
        *reinterpret_cast<float4*>(row + 4) = r1;
    }
    __syncthreads();

    // --- Phase C: coalesced contiguous store of this quarter's output slab ---
    float* outp = out + (size_t)n * (CC * NBINS) + (size_t)quarter * (QC * NBINS);
    #pragma unroll 1
    for (int i = tid; i < QC * NBINS; i += 256) {
        const int c = i / NBINS;      // local channel 0..63
        const int j = i - c * NBINS;  // bin 0..48
        outp[i] = s_out[j * RPITCH + c];
    }
}

// ---------------------------------------------------------------------------
extern "C" void kernel_launch(void* const* d_in, const int* in_sizes, int n_in,
                              void* d_out, int out_size) {
    const float* features;
    const float* rois;
    int rois_elems;
    if (in_sizes[0] > in_sizes[1]) {
        features = (const float*)d_in[0];
        rois     = (const float*)d_in[1];
        rois_elems = in_sizes[1];
    } else {
        features = (const float*)d_in[1];
        rois     = (const float*)d_in[0];
        rois_elems = in_sizes[0];
    }
    const int N = rois_elems / 6;

    dim3 tgrid(HWSZ / 32, CC / 32, BB);
    dim3 tblk(32, 8);
    nchw_to_nhwc_half_kernel<<<tgrid, tblk>>>(features);

    roi_align_rotated_kernel<<<N * 4, 256>>>(rois, (float*)d_out, N);
}

// round 15
// speedup vs baseline: 1.7407x; 1.0005x over previous
#include <cuda_runtime.h>
#include <cuda_fp16.h>
#include <cuda_bf16.h>
#include <math.h>

// Problem constants (fixed by the dataset)
#define BB 2
#define CC 256
#define HH 200
#define WW 200
#define HWSZ (HH * WW)          // 40000
#define OUT_H 7
#define OUT_W 7
#define GSAMP 2
#define NSAMP (OUT_H * GSAMP * OUT_W * GSAMP)  // 196
#define SPATIAL_SCALE 0.25f
#define NBINS (OUT_H * OUT_W)   // 49
#define QC 64                   // channels per CTA (quarter)
#define RPITCH 68               // 64 + 4 floats per staging row (16B-aligned rows)

// NHWC fp16 scratch: 2*200*200*256 halves = 40.96 MB (static device array: allowed)
__device__ __align__(16) __half g_featT[(size_t)BB * HWSZ * CC];

__device__ __forceinline__ __half2 u2h(unsigned int u) {
    __half2 h; *reinterpret_cast<unsigned int*>(&h) = u; return h;
}
__device__ __forceinline__ unsigned int h2u(__half2 h) {
    return *reinterpret_cast<unsigned int*>(&h);
}

// ---------------------------------------------------------------------------
// Kernel 1: NCHW fp32 -> NHWC fp16 transpose (tiled 32x32, coalesced, half2
// vectorized stores). Proven conflict-free; ~123MB DRAM traffic.
// ---------------------------------------------------------------------------
__global__ void nchw_to_nhwc_half_kernel(const float* __restrict__ in) {
    __shared__ float tile[32][33];
    const int b  = blockIdx.z;
    const int p0 = blockIdx.x * 32;   // spatial tile origin
    const int c0 = blockIdx.y * 32;   // channel tile origin
    const int tx = threadIdx.x;       // 0..31
    const int ty = threadIdx.y;       // 0..7
    const int tid = ty * 32 + tx;

    const float* src = in + (size_t)b * CC * HWSZ;
    __half* dst = g_featT + (size_t)b * HWSZ * CC;

    #pragma unroll
    for (int i = 0; i < 32; i += 8)
        tile[ty + i][tx] = src[(size_t)(c0 + ty + i) * HWSZ + (p0 + tx)];
    __syncthreads();

    #pragma unroll
    for (int it = 0; it < 2; it++) {
        const int e  = it * 256 + tid;
        const int pl = e >> 4;        // local position 0..31
        const int h  = e & 15;        // half2 index within 32 channels
        const float f0 = tile[2 * h][pl];
        const float f1 = tile[2 * h + 1][pl];
        __half2 v = __floats2half2_rn(f0, f1);
        *reinterpret_cast<__half2*>(dst + (size_t)(p0 + pl) * CC + c0 + 2 * h) = v;
    }
}

// ---------------------------------------------------------------------------
// Kernel 2: RoIAlignRotated gather, fp16 features + half2 bilinear math.
// grid = 4N: CTA = (roi n, 64-channel quarter). 256 threads.
// Thread t: oct q = t & 7 (8 local channels), bin group bg = t >> 3 (0..31),
//           bins j = bg, bg+32 (j < 49).
// launch_bounds(256,6): regs ~39 (NO forced spill — R12 lesson), smem ~19.6KB
// -> 6 CTAs/SM. Finer CTAs cut wave-quantization tail (4000 vs 2000 CTAs).
// ---------------------------------------------------------------------------
__global__ __launch_bounds__(256, 6)
void roi_align_rotated_kernel(const float* __restrict__ rois,
                              float* __restrict__ out,
                              int N) {
    __shared__ uint4 s_wh[NSAMP];             // 4 duplicated-half2 weights
    __shared__ int4  s_i[NSAMP];              // oct (16B) indices
    __shared__ float s_out[NBINS * RPITCH];   // 13328 B

    const int n       = blockIdx.x >> 2;
    const int quarter = blockIdx.x & 3;
    const int tid     = threadIdx.x;
    const int q       = tid & 7;              // local oct 0..7
    const int bg      = tid >> 3;              // 0..31

    // --- roi params (broadcast) ---
    const float* R = rois + (size_t)n * 6;
    const int   b     = (int)R[0];
    const float cx    = R[1] * SPATIAL_SCALE;
    const float cy    = R[2] * SPATIAL_SCALE;
    const float rw    = fmaxf(R[3] * SPATIAL_SCALE, 1.0f);
    const float rh    = fmaxf(R[4] * SPATIAL_SCALE, 1.0f);
    const float theta = R[5];
    const float cost  = cosf(theta);
    const float sint  = sinf(theta);
    const float bin_h = rh * (1.0f / OUT_H);
    const float bin_w = rw * (1.0f / OUT_W);

    // --- Phase A: sample-point precompute (reference semantics exactly) ---
    if (tid < NSAMP) {
        const int s = tid;
        const int r = s / (OUT_W * GSAMP);
        const int p = s % (OUT_W * GSAMP);
        const float sy = ((float)r + 0.5f) * (1.0f / GSAMP);
        const float sx = ((float)p + 0.5f) * (1.0f / GSAMP);
        const float yy = -rh * 0.5f + sy * bin_h;
        const float xx = -rw * 0.5f + sx * bin_w;
        const float y = yy * cost - xx * sint + cy;
        const float x = yy * sint + xx * cost + cx;

        const bool inside = (y >= -1.0f) && (y <= (float)HH) &&
                            (x >= -1.0f) && (x <= (float)WW);

        const float yc = fmaxf(y, 0.0f);
        const float xc = fmaxf(x, 0.0f);
        const float fy = floorf(yc);
        const float fx = floorf(xc);
        int yl = min((int)fy, HH - 1);
        int xl = min((int)fx, WW - 1);
        const int yh = min(yl + 1, HH - 1);
        const int xh = min(xl + 1, WW - 1);
        const float ly = (fy >= (float)(HH - 1)) ? 0.0f : (yc - (float)yl);
        const float lx = (fx >= (float)(WW - 1)) ? 0.0f : (xc - (float)xl);
        const float hy = 1.0f - ly;
        const float hx = 1.0f - lx;

        float w1 = hy * hx, w2 = hy * lx, w3 = ly * hx, w4 = ly * lx;
        if (!inside) { w1 = 0.f; w2 = 0.f; w3 = 0.f; w4 = 0.f; }

        uint4 wh;
        wh.x = h2u(__float2half2_rn(w1));   // (w1, w1)
        wh.y = h2u(__float2half2_rn(w2));
        wh.z = h2u(__float2half2_rn(w3));
        wh.w = h2u(__float2half2_rn(w4));

        // index in oct (16B) units: pos * (CC/8) = pos * 32
        const int base = b * HWSZ;
        int4 idx;
        idx.x = (base + yl * WW + xl) * (CC / 8);
        idx.y = (base + yl * WW + xh) * (CC / 8);
        idx.z = (base + yh * WW + xl) * (CC / 8);
        idx.w = (base + yh * WW + xh) * (CC / 8);
        s_i[s]  = idx;
        s_wh[s] = wh;
    }
    __syncthreads();

    // --- Phase B: fp16 oct gather, half2 bilinear, fp32 cross-sample acc ---
    const uint4* __restrict__ ft8 =
        reinterpret_cast<const uint4*>(g_featT) + (quarter * 8 + q);

    #pragma unroll 1
    for (int j = bg; j < NBINS; j += 32) {
        const int ph = j / OUT_W;
        const int pw = j - ph * OUT_W;
        const int s00 = (2 * ph) * (OUT_W * GSAMP) + 2 * pw;

        float acc[8];
        #pragma unroll
        for (int k = 0; k < 8; k++) acc[k] = 0.0f;

        #pragma unroll
        for (int iy = 0; iy < GSAMP; iy++) {
            #pragma unroll
            for (int ix = 0; ix < GSAMP; ix++) {
                const int s = s00 + iy * (OUT_W * GSAMP) + ix;
                const int4  ii = s_i[s];    // LDS.128 broadcast
                const uint4 wh = s_wh[s];   // LDS.128 broadcast
                const __half2 w1 = u2h(wh.x);
                const __half2 w2 = u2h(wh.y);
                const __half2 w3 = u2h(wh.z);
                const __half2 w4 = u2h(wh.w);
                const uint4 u1 = __ldg(ft8 + ii.x);
                const uint4 u2 = __ldg(ft8 + ii.y);
                const uint4 u3 = __ldg(ft8 + ii.z);
                const uint4 u4 = __ldg(ft8 + ii.w);
                const __half2* h1 = reinterpret_cast<const __half2*>(&u1);
                const __half2* h2 = reinterpret_cast<const __half2*>(&u2);
                const __half2* h3 = reinterpret_cast<const __half2*>(&u3);
                const __half2* h4 = reinterpret_cast<const __half2*>(&u4);
                #pragma unroll
                for (int k = 0; k < 4; k++) {
                    __half2 t = __hmul2(h1[k], w1);
                    t = __hfma2(h2[k], w2, t);
                    t = __hfma2(h3[k], w3, t);
                    t = __hfma2(h4[k], w4, t);
                    const float2 f = __half22float2(t);
                    acc[2*k]   += f.x;
                    acc[2*k+1] += f.y;
                }
            }
        }
        float4 r0 = make_float4(acc[0] * 0.25f, acc[1] * 0.25f,
                                acc[2] * 0.25f, acc[3] * 0.25f);
        float4 r1 = make_float4(acc[4] * 0.25f, acc[5] * 0.25f,
                                acc[6] * 0.25f, acc[7] * 0.25f);
        float* row = &s_out[j * RPITCH + 8 * q];
        *reinterpret_cast<float4*>(row)     = r0;
        *reinterpret_cast<float4*>(row + 4) = r1;
    }
    __syncthreads();

    // --- Phase C: coalesced contiguous store of this quarter's output slab ---
    float* outp = out + (size_t)n * (CC * NBINS) + (size_t)quarter * (QC * NBINS);
    #pragma unroll 1
    for (int i = tid; i < QC * NBINS; i += 256) {
        const int c = i / NBINS;      // local channel 0..63
        const int j = i - c * NBINS;  // bin 0..48
        outp[i] = s_out[j * RPITCH + c];
    }
}

// ---------------------------------------------------------------------------
extern "C" void kernel_launch(void* const* d_in, const int* in_sizes, int n_in,
                              void* d_out, int out_size) {
    const float* features;
    const float* rois;
    int rois_elems;
    if (in_sizes[0] > in_sizes[1]) {
        features = (const float*)d_in[0];
        rois     = (const float*)d_in[1];
        rois_elems = in_sizes[1];
    } else {
        features = (const float*)d_in[1];
        rois     = (const float*)d_in[0];
        rois_elems = in_sizes[0];
    }
    const int N = rois_elems / 6;

    dim3 tgrid(HWSZ / 32, CC / 32, BB);
    dim3 tblk(32, 8);
    nchw_to_nhwc_half_kernel<<<tgrid, tblk>>>(features);

    roi_align_rotated_kernel<<<N * 4, 256>>>(rois, (float*)d_out, N);
}

// round 16
// speedup vs baseline: 1.8018x; 1.0351x over previous
#include <cuda_runtime.h>
#include <cuda_fp16.h>
#include <cuda_bf16.h>
#include <math.h>

// Problem constants (fixed by the dataset)
#define BB 2
#define CC 256
#define HH 200
#define WW 200
#define HWSZ (HH * WW)          // 40000
#define OUT_H 7
#define OUT_W 7
#define GSAMP 2
#define NSAMP (OUT_H * GSAMP * OUT_W * GSAMP)  // 196
#define SPATIAL_SCALE 0.25f
#define NBINS (OUT_H * OUT_W)   // 49
#define QC 64                   // channels per CTA (quarter)
#define RPITCH 68               // 64 + 4 floats per staging row

// NHWC fp16 scratch: 2*200*200*256 halves = 40.96 MB (static device array: allowed)
__device__ __align__(16) __half g_featT[(size_t)BB * HWSZ * CC];

__device__ __forceinline__ __half2 u2h(unsigned int u) {
    __half2 h; *reinterpret_cast<unsigned int*>(&h) = u; return h;
}
__device__ __forceinline__ unsigned int h2u(__half2 h) {
    return *reinterpret_cast<unsigned int*>(&h);
}

// ---------------------------------------------------------------------------
// Kernel 1: NCHW fp32 -> NHWC fp16 transpose (tiled 32x32, coalesced, half2
// vectorized stores). ~123MB DRAM traffic, near memory floor.
// ---------------------------------------------------------------------------
__global__ void nchw_to_nhwc_half_kernel(const float* __restrict__ in) {
    __shared__ float tile[32][33];
    const int b  = blockIdx.z;
    const int p0 = blockIdx.x * 32;   // spatial tile origin
    const int c0 = blockIdx.y * 32;   // channel tile origin
    const int tx = threadIdx.x;       // 0..31
    const int ty = threadIdx.y;       // 0..7
    const int tid = ty * 32 + tx;

    const float* src = in + (size_t)b * CC * HWSZ;
    __half* dst = g_featT + (size_t)b * HWSZ * CC;

    #pragma unroll
    for (int i = 0; i < 32; i += 8)
        tile[ty + i][tx] = src[(size_t)(c0 + ty + i) * HWSZ + (p0 + tx)];
    __syncthreads();

    #pragma unroll
    for (int it = 0; it < 2; it++) {
        const int e  = it * 256 + tid;
        const int pl = e >> 4;        // local position 0..31
        const int h  = e & 15;        // half2 index within 32 channels
        const float f0 = tile[2 * h][pl];
        const float f1 = tile[2 * h + 1][pl];
        __half2 v = __floats2half2_rn(f0, f1);
        *reinterpret_cast<__half2*>(dst + (size_t)(p0 + pl) * CC + c0 + 2 * h) = v;
    }
}

// ---------------------------------------------------------------------------
// Kernel 2: RoIAlignRotated gather, fp16 features, flat HFMA2 reduction.
// grid = 4N: CTA = (roi n, 64-channel quarter). 256 threads.
// Thread t: oct q = t & 7 (8 local channels), bin group bg = t >> 3 (0..31).
// Weights pre-scaled by 0.25; each bin = sum of 16 (w*corner) terms,
// accumulated in TWO half2 chains of 8 (precision), combined in fp32.
// ---------------------------------------------------------------------------
__global__ __launch_bounds__(256, 6)
void roi_align_rotated_kernel(const float* __restrict__ rois,
                              float* __restrict__ out,
                              int N) {
    __shared__ uint4 s_wh[NSAMP];             // 4 duplicated-half2 weights (x0.25)
    __shared__ int4  s_i[NSAMP];              // oct (16B) indices
    __shared__ float s_out[NBINS * RPITCH];   // 13328 B

    const int n       = blockIdx.x >> 2;
    const int quarter = blockIdx.x & 3;
    const int tid     = threadIdx.x;
    const int q       = tid & 7;              // local oct 0..7
    const int bg      = tid >> 3;             // 0..31

    // --- roi params (broadcast) ---
    const float* R = rois + (size_t)n * 6;
    const int   b     = (int)R[0];
    const float cx    = R[1] * SPATIAL_SCALE;
    const float cy    = R[2] * SPATIAL_SCALE;
    const float rw    = fmaxf(R[3] * SPATIAL_SCALE, 1.0f);
    const float rh    = fmaxf(R[4] * SPATIAL_SCALE, 1.0f);
    const float theta = R[5];
    const float cost  = cosf(theta);
    const float sint  = sinf(theta);
    const float bin_h = rh * (1.0f / OUT_H);
    const float bin_w = rw * (1.0f / OUT_W);

    // --- Phase A: sample-point precompute (reference semantics exactly) ---
    if (tid < NSAMP) {
        const int s = tid;
        const int r = s / (OUT_W * GSAMP);
        const int p = s % (OUT_W * GSAMP);
        const float sy = ((float)r + 0.5f) * (1.0f / GSAMP);
        const float sx = ((float)p + 0.5f) * (1.0f / GSAMP);
        const float yy = -rh * 0.5f + sy * bin_h;
        const float xx = -rw * 0.5f + sx * bin_w;
        const float y = yy * cost - xx * sint + cy;
        const float x = yy * sint + xx * cost + cx;

        const bool inside = (y >= -1.0f) && (y <= (float)HH) &&
                            (x >= -1.0f) && (x <= (float)WW);

        const float yc = fmaxf(y, 0.0f);
        const float xc = fmaxf(x, 0.0f);
        const float fy = floorf(yc);
        const float fx = floorf(xc);
        int yl = min((int)fy, HH - 1);
        int xl = min((int)fx, WW - 1);
        const int yh = min(yl + 1, HH - 1);
        const int xh = min(xl + 1, WW - 1);
        const float ly = (fy >= (float)(HH - 1)) ? 0.0f : (yc - (float)yl);
        const float lx = (fx >= (float)(WW - 1)) ? 0.0f : (xc - (float)xl);
        const float hy = 1.0f - ly;
        const float hx = 1.0f - lx;

        // fold the 1/4 sample mean into the weights
        float w1 = hy * hx * 0.25f, w2 = hy * lx * 0.25f;
        float w3 = ly * hx * 0.25f, w4 = ly * lx * 0.25f;
        if (!inside) { w1 = 0.f; w2 = 0.f; w3 = 0.f; w4 = 0.f; }

        uint4 wh;
        wh.x = h2u(__float2half2_rn(w1));   // (w1, w1)
        wh.y = h2u(__float2half2_rn(w2));
        wh.z = h2u(__float2half2_rn(w3));
        wh.w = h2u(__float2half2_rn(w4));

        // index in oct (16B) units: pos * (CC/8) = pos * 32
        const int base = b * HWSZ;
        int4 idx;
        idx.x = (base + yl * WW + xl) * (CC / 8);
        idx.y = (base + yl * WW + xh) * (CC / 8);
        idx.z = (base + yh * WW + xl) * (CC / 8);
        idx.w = (base + yh * WW + xh) * (CC / 8);
        s_i[s]  = idx;
        s_wh[s] = wh;
    }
    __syncthreads();

    // --- Phase B: fp16 oct gather, flat HFMA2 accumulation (2 chains) ---
    const uint4* __restrict__ ft8 =
        reinterpret_cast<const uint4*>(g_featT) + (quarter * 8 + q);

    #pragma unroll 1
    for (int j = bg; j < NBINS; j += 32) {
        const int ph = j / OUT_W;
        const int pw = j - ph * OUT_W;
        const int s00 = (2 * ph) * (OUT_W * GSAMP) + 2 * pw;

        const __half2 hzero = __float2half2_rn(0.0f);
        __half2 accA[4], accB[4];
        #pragma unroll
        for (int k = 0; k < 4; k++) { accA[k] = hzero; accB[k] = hzero; }

        #pragma unroll
        for (int iy = 0; iy < GSAMP; iy++) {
            #pragma unroll
            for (int ix = 0; ix < GSAMP; ix++) {
                const int s = s00 + iy * (OUT_W * GSAMP) + ix;
                const int4  ii = s_i[s];    // LDS.128 broadcast
                const uint4 wh = s_wh[s];   // LDS.128 broadcast
                const __half2 w1 = u2h(wh.x);
                const __half2 w2 = u2h(wh.y);
                const __half2 w3 = u2h(wh.z);
                const __half2 w4 = u2h(wh.w);
                const uint4 u1 = __ldg(ft8 + ii.x);
                const uint4 u2 = __ldg(ft8 + ii.y);
                const uint4 u3 = __ldg(ft8 + ii.z);
                const uint4 u4 = __ldg(ft8 + ii.w);
                const __half2* h1 = reinterpret_cast<const __half2*>(&u1);
                const __half2* h2 = reinterpret_cast<const __half2*>(&u2);
                const __half2* h3 = reinterpret_cast<const __half2*>(&u3);
                const __half2* h4 = reinterpret_cast<const __half2*>(&u4);
                __half2* acc = (iy == 0) ? accA : accB;  // chain split
                #pragma unroll
                for (int k = 0; k < 4; k++) {
                    __half2 t = acc[k];
                    t = __hfma2(h1[k], w1, t);
                    t = __hfma2(h2[k], w2, t);
                    t = __hfma2(h3[k], w3, t);
                    t = __hfma2(h4[k], w4, t);
                    acc[k] = t;
                }
            }
        }
        // combine the two half2 chains in fp32, stage bin-major
        float res[8];
        #pragma unroll
        for (int k = 0; k < 4; k++) {
            const float2 fa = __half22float2(accA[k]);
            const float2 fb = __half22float2(accB[k]);
            res[2*k]   = fa.x + fb.x;
            res[2*k+1] = fa.y + fb.y;
        }
        float4 r0 = make_float4(res[0], res[1], res[2], res[3]);
        float4 r1 = make_float4(res[4], res[5], res[6], res[7]);
        float* row = &s_out[j * RPITCH + 8 * q];
        *reinterpret_cast<float4*>(row)     = r0;
        *reinterpret_cast<float4*>(row + 4) = r1;
    }
    __syncthreads();

    // --- Phase C: coalesced contiguous store of this quarter's output slab ---
    float* outp = out + (size_t)n * (CC * NBINS) + (size_t)quarter * (QC * NBINS);
    #pragma unroll 1
    for (int i = tid; i < QC * NBINS; i += 256) {
        const int c = i / NBINS;      // local channel 0..63
        const int j = i - c * NBINS;  // bin 0..48
        outp[i] = s_out[j * RPITCH + c];
    }
}

// ---------------------------------------------------------------------------
extern "C" void kernel_launch(void* const* d_in, const int* in_sizes, int n_in,
                              void* d_out, int out_size) {
    const float* features;
    const float* rois;
    int rois_elems;
    if (in_sizes[0] > in_sizes[1]) {
        features = (const float*)d_in[0];
        rois     = (const float*)d_in[1];
        rois_elems = in_sizes[1];
    } else {
        features = (const float*)d_in[1];
        rois     = (const float*)d_in[0];
        rois_elems = in_sizes[0];
    }
    const int N = rois_elems / 6;

    dim3 tgrid(HWSZ / 32, CC / 32, BB);
    dim3 tblk(32, 8);
    nchw_to_nhwc_half_kernel<<<tgrid, tblk>>>(features);

    roi_align_rotated_kernel<<<N * 4, 256>>>(rois, (float*)d_out, N);
}

// round 17
// speedup vs baseline: 2.0591x; 1.1428x over previous
#include <cuda_runtime.h>
#include <cuda_fp16.h>
#include <cuda_bf16.h>
#include <math.h>

// Problem constants (fixed by the dataset)
#define BB 2
#define CC 256
#define HH 200
#define WW 200
#define HWSZ (HH * WW)          // 40000
#define OUT_H 7
#define OUT_W 7
#define GSAMP 2
#define NSAMP (OUT_H * GSAMP * OUT_W * GSAMP)  // 196
#define SPATIAL_SCALE 0.25f
#define NBINS (OUT_H * OUT_W)   // 49
#define QC 64                   // channels per CTA (quarter)
#define RPITCH 68               // 64 + 4 floats per staging row

// NHWC fp16 scratch: 2*200*200*256 halves = 40.96 MB (static device array: allowed)
__device__ __align__(16) __half g_featT[(size_t)BB * HWSZ * CC];

__device__ __forceinline__ __half2 u2h(unsigned int u) {
    __half2 h; *reinterpret_cast<unsigned int*>(&h) = u; return h;
}
__device__ __forceinline__ unsigned int h2u(__half2 h) {
    return *reinterpret_cast<unsigned int*>(&h);
}

// ---------------------------------------------------------------------------
// Kernel 1: NCHW fp32 -> NHWC fp16 transpose via register 4x4 blocks.
// No shared memory, no syncs.
// Thread owns channels c..c+3 x positions p..p+3:
//   read : 4x LDG.128 (float4 along p, one per channel row)
//          -> per warp instr: 4 x 128B fully-used wavefronts
//   write: 4x STG.64 (4 half channels at one position)
//          -> per warp instr: 8 x 32B fully-used sectors
// Grid: (HWSZ/32, CC/128, BB) x 256 threads.
// ---------------------------------------------------------------------------
__global__ __launch_bounds__(256)
void nchw_to_nhwc_half_kernel(const float* __restrict__ in) {
    const int b    = blockIdx.z;
    const int cT   = blockIdx.y;            // 128-channel tile (0..1)
    const int p0   = blockIdx.x * 32;       // position tile origin
    const int w    = threadIdx.x >> 5;      // warp 0..7
    const int lane = threadIdx.x & 31;
    const int p4   = lane & 7;               // position sub-block 0..7
    const int cb   = lane >> 3;              // channel sub-block 0..3
    const int c    = cT * 128 + w * 16 + cb * 4;
    const int p    = p0 + p4 * 4;

    const float* src = in + (size_t)b * CC * HWSZ + (size_t)c * HWSZ + p;
    const float4 v0 = __ldg(reinterpret_cast<const float4*>(src));
    const float4 v1 = __ldg(reinterpret_cast<const float4*>(src + HWSZ));
    const float4 v2 = __ldg(reinterpret_cast<const float4*>(src + 2 * HWSZ));
    const float4 v3 = __ldg(reinterpret_cast<const float4*>(src + 3 * HWSZ));

    __half* dst = g_featT + (size_t)b * HWSZ * CC + (size_t)p * CC + c;

    uint2 pk;
    // position p+0: channels (v0.x, v1.x, v2.x, v3.x)
    pk.x = h2u(__floats2half2_rn(v0.x, v1.x));
    pk.y = h2u(__floats2half2_rn(v2.x, v3.x));
    *reinterpret_cast<uint2*>(dst) = pk;
    // position p+1
    pk.x = h2u(__floats2half2_rn(v0.y, v1.y));
    pk.y = h2u(__floats2half2_rn(v2.y, v3.y));
    *reinterpret_cast<uint2*>(dst + CC) = pk;
    // position p+2
    pk.x = h2u(__floats2half2_rn(v0.z, v1.z));
    pk.y = h2u(__floats2half2_rn(v2.z, v3.z));
    *reinterpret_cast<uint2*>(dst + 2 * CC) = pk;
    // position p+3
    pk.x = h2u(__floats2half2_rn(v0.w, v1.w));
    pk.y = h2u(__floats2half2_rn(v2.w, v3.w));
    *reinterpret_cast<uint2*>(dst + 3 * CC) = pk;
}

// ---------------------------------------------------------------------------
// Kernel 2: RoIAlignRotated gather, fp16 features, flat HFMA2 reduction.
// (unchanged from R16 — 35.3us, L1-bound)
// grid = 4N: CTA = (roi n, 64-channel quarter). 256 threads.
// Thread t: oct q = t & 7 (8 local channels), bin group bg = t >> 3 (0..31).
// Weights pre-scaled by 0.25; each bin = sum of 16 (w*corner) terms,
// accumulated in TWO half2 chains of 8 (precision), combined in fp32.
// ---------------------------------------------------------------------------
__global__ __launch_bounds__(256, 6)
void roi_align_rotated_kernel(const float* __restrict__ rois,
                              float* __restrict__ out,
                              int N) {
    __shared__ uint4 s_wh[NSAMP];             // 4 duplicated-half2 weights (x0.25)
    __shared__ int4  s_i[NSAMP];              // oct (16B) indices
    __shared__ float s_out[NBINS * RPITCH];   // 13328 B

    const int n       = blockIdx.x >> 2;
    const int quarter = blockIdx.x & 3;
    const int tid     = threadIdx.x;
    const int q       = tid & 7;              // local oct 0..7
    const int bg      = tid >> 3;             // 0..31

    // --- roi params (broadcast) ---
    const float* R = rois + (size_t)n * 6;
    const int   b     = (int)R[0];
    const float cx    = R[1] * SPATIAL_SCALE;
    const float cy    = R[2] * SPATIAL_SCALE;
    const float rw    = fmaxf(R[3] * SPATIAL_SCALE, 1.0f);
    const float rh    = fmaxf(R[4] * SPATIAL_SCALE, 1.0f);
    const float theta = R[5];
    const float cost  = cosf(theta);
    const float sint  = sinf(theta);
    const float bin_h = rh * (1.0f / OUT_H);
    const float bin_w = rw * (1.0f / OUT_W);

    // --- Phase A: sample-point precompute (reference semantics exactly) ---
    if (tid < NSAMP) {
        const int s = tid;
        const int r = s / (OUT_W * GSAMP);
        const int p = s % (OUT_W * GSAMP);
        const float sy = ((float)r + 0.5f) * (1.0f / GSAMP);
        const float sx = ((float)p + 0.5f) * (1.0f / GSAMP);
        const float yy = -rh * 0.5f + sy * bin_h;
        const float xx = -rw * 0.5f + sx * bin_w;
        const float y = yy * cost - xx * sint + cy;
        const float x = yy * sint + xx * cost + cx;

        const bool inside = (y >= -1.0f) && (y <= (float)HH) &&
                            (x >= -1.0f) && (x <= (float)WW);

        const float yc = fmaxf(y, 0.0f);
        const float xc = fmaxf(x, 0.0f);
        const float fy = floorf(yc);
        const float fx = floorf(xc);
        int yl = min((int)fy, HH - 1);
        int xl = min((int)fx, WW - 1);
        const int yh = min(yl + 1, HH - 1);
        const int xh = min(xl + 1, WW - 1);
        const float ly = (fy >= (float)(HH - 1)) ? 0.0f : (yc - (float)yl);
        const float lx = (fx >= (float)(WW - 1)) ? 0.0f : (xc - (float)xl);
        const float hy = 1.0f - ly;
        const float hx = 1.0f - lx;

        // fold the 1/4 sample mean into the weights
        float w1 = hy * hx * 0.25f, w2 = hy * lx * 0.25f;
        float w3 = ly * hx * 0.25f, w4 = ly * lx * 0.25f;
        if (!inside) { w1 = 0.f; w2 = 0.f; w3 = 0.f; w4 = 0.f; }

        uint4 wh;
        wh.x = h2u(__float2half2_rn(w1));   // (w1, w1)
        wh.y = h2u(__float2half2_rn(w2));
        wh.z = h2u(__float2half2_rn(w3));
        wh.w = h2u(__float2half2_rn(w4));

        // index in oct (16B) units: pos * (CC/8) = pos * 32
        const int base = b * HWSZ;
        int4 idx;
        idx.x = (base + yl * WW + xl) * (CC / 8);
        idx.y = (base + yl * WW + xh) * (CC / 8);
        idx.z = (base + yh * WW + xl) * (CC / 8);
        idx.w = (base + yh * WW + xh) * (CC / 8);
        s_i[s]  = idx;
        s_wh[s] = wh;
    }
    __syncthreads();

    // --- Phase B: fp16 oct gather, flat HFMA2 accumulation (2 chains) ---
    const uint4* __restrict__ ft8 =
        reinterpret_cast<const uint4*>(g_featT) + (quarter * 8 + q);

    #pragma unroll 1
    for (int j = bg; j < NBINS; j += 32) {
        const int ph = j / OUT_W;
        const int pw = j - ph * OUT_W;
        const int s00 = (2 * ph) * (OUT_W * GSAMP) + 2 * pw;

        const __half2 hzero = __float2half2_rn(0.0f);
        __half2 accA[4], accB[4];
        #pragma unroll
        for (int k = 0; k < 4; k++) { accA[k] = hzero; accB[k] = hzero; }

        #pragma unroll
        for (int iy = 0; iy < GSAMP; iy++) {
            #pragma unroll
            for (int ix = 0; ix < GSAMP; ix++) {
                const int s = s00 + iy * (OUT_W * GSAMP) + ix;
                const int4  ii = s_i[s];    // LDS.128 broadcast
                const uint4 wh = s_wh[s];   // LDS.128 broadcast
                const __half2 w1 = u2h(wh.x);
                const __half2 w2 = u2h(wh.y);
                const __half2 w3 = u2h(wh.z);
                const __half2 w4 = u2h(wh.w);
                const uint4 u1 = __ldg(ft8 + ii.x);
                const uint4 u2 = __ldg(ft8 + ii.y);
                const uint4 u3 = __ldg(ft8 + ii.z);
                const uint4 u4 = __ldg(ft8 + ii.w);
                const __half2* h1 = reinterpret_cast<const __half2*>(&u1);
                const __half2* h2 = reinterpret_cast<const __half2*>(&u2);
                const __half2* h3 = reinterpret_cast<const __half2*>(&u3);
                const __half2* h4 = reinterpret_cast<const __half2*>(&u4);
                __half2* acc = (iy == 0) ? accA : accB;  // chain split
                #pragma unroll
                for (int k = 0; k < 4; k++) {
                    __half2 t = acc[k];
                    t = __hfma2(h1[k], w1, t);
                    t = __hfma2(h2[k], w2, t);
                    t = __hfma2(h3[k], w3, t);
                    t = __hfma2(h4[k], w4, t);
                    acc[k] = t;
                }
            }
        }
        // combine the two half2 chains in fp32, stage bin-major
        float res[8];
        #pragma unroll
        for (int k = 0; k < 4; k++) {
            const float2 fa = __half22float2(accA[k]);
            const float2 fb = __half22float2(accB[k]);
            res[2*k]   = fa.x + fb.x;
            res[2*k+1] = fa.y + fb.y;
        }
        float4 r0 = make_float4(res[0], res[1], res[2], res[3]);
        float4 r1 = make_float4(res[4], res[5], res[6], res[7]);
        float* row = &s_out[j * RPITCH + 8 * q];
        *reinterpret_cast<float4*>(row)     = r0;
        *reinterpret_cast<float4*>(row + 4) = r1;
    }
    __syncthreads();

    // --- Phase C: coalesced contiguous store of this quarter's output slab ---
    float* outp = out + (size_t)n * (CC * NBINS) + (size_t)quarter * (QC * NBINS);
    #pragma unroll 1
    for (int i = tid; i < QC * NBINS; i += 256) {
        const int c = i / NBINS;      // local channel 0..63
        const int j = i - c * NBINS;  // bin 0..48
        outp[i] = s_out[j * RPITCH + c];
    }
}

// ---------------------------------------------------------------------------
extern "C" void kernel_launch(void* const* d_in, const int* in_sizes, int n_in,
                              void* d_out, int out_size) {
    const float* features;
    const float* rois;
    int rois_elems;
    if (in_sizes[0] > in_sizes[1]) {
        features = (const float*)d_in[0];
        rois     = (const float*)d_in[1];
        rois_elems = in_sizes[1];
    } else {
        features = (const float*)d_in[1];
        rois     = (const float*)d_in[0];
        rois_elems = in_sizes[0];
    }
    const int N = rois_elems / 6;

    dim3 tgrid(HWSZ / 32, CC / 128, BB);   // 1250 x 2 x 2 = 5000 CTAs
    nchw_to_nhwc_half_kernel<<<tgrid, 256>>>(features);

    roi_align_rotated_kernel<<<N * 4, 256>>>(rois, (float*)d_out, N);
}